// round 12
// baseline (speedup 1.0000x reference)
#include <cuda_runtime.h>
#include <cuda_fp16.h>
#include <cstdint>

#define VOCAB 100000
#define EMBED 128
#define ROWS  12800   // 64*200
#define K_ITEMS 50
#define K_PAD 56      // padded; pad ids -> 0 -> zero WT row

#define N_CHUNKS 4    // 4 chunks of 32 embed dims
#define VT 80         // v per transpose tile
#define F4T 20        // float4 per e-row per tile
#define ET 32         // e per chunk
#define T_PER_CHUNK (VOCAB / VT)     // 1250
#define G_RPB 4
#define G_PER_CHUNK (ROWS / G_RPB)   // 3200
#define NTHREADS 128
#define NBLOCKS (N_CHUNKS * T_PER_CHUNK + N_CHUNKS * G_PER_CHUNK)   // 17800

// 25.6 MB scratch: WT[V][128] fp16, row 0 zeroed (id==0 masked).
__device__ __align__(256) __half g_WT[(size_t)VOCAB * EMBED];

// Per-chunk ready counters + completion counter. Zero-initialized; the last
// block of every launch resets them, so each call/replay sees identical state.
__device__ int g_ready[N_CHUNKS];
__device__ int g_done;

__device__ __forceinline__ int ld_acquire(const int* p) {
    int v;
    asm volatile("ld.acquire.gpu.b32 %0, [%1];" : "=r"(v) : "l"(p));
    return v;
}

__device__ __forceinline__ int swz(int v, int e) {
    return v * 32 + ((e + v + (v >> 2)) & 31);
}

// bid layout: T0 [0,1250) T1 [1250,2500) G0 [2500,5700) T2 [5700,6950)
//             G1 [6950,10150) T3 [10150,11400) G2 [11400,14600) G3 [14600,17800)
// Every T(c) precedes its G(c) in bid order -> in-order dispatch guarantees
// the dependency is satisfiable; gather blocks briefly spin on g_ready[c].
__global__ __launch_bounds__(NTHREADS, 10) void fused(
    const float4* __restrict__ W4,     // W [128, 100000] fp32
    const int*    __restrict__ ids,    // [ROWS, 50]
    const float*  __restrict__ bias,   // [128]
    float*        __restrict__ out)    // [ROWS, 128]
{
    __shared__ float s_ts[VT * 32];              // 10 KB transpose staging
    int* s_ids = (int*)s_ts;                     // gather reuses: [G_RPB][K_PAD]

    const int tid = threadIdx.x;
    const int bid = blockIdx.x;

    int isT, chunk, tile;
    if      (bid < 1250)  { isT = 1; chunk = 0; tile = bid; }
    else if (bid < 2500)  { isT = 1; chunk = 1; tile = bid - 1250; }
    else if (bid < 5700)  { isT = 0; chunk = 0; tile = bid - 2500; }
    else if (bid < 6950)  { isT = 1; chunk = 2; tile = bid - 5700; }
    else if (bid < 10150) { isT = 0; chunk = 1; tile = bid - 6950; }
    else if (bid < 11400) { isT = 1; chunk = 3; tile = bid - 10150; }
    else if (bid < 14600) { isT = 0; chunk = 2; tile = bid - 11400; }
    else                  { isT = 0; chunk = 3; tile = bid - 14600; }

    if (isT) {
        // ---- Transpose tile: 32 E x 80 V, W fp32 -> WT fp16 ----
        const int vt4 = tile * F4T;
        const int vt  = tile * VT;
        const int et  = chunk * ET;

        #pragma unroll
        for (int i = 0; i < 5; i++) {
            const int idx = i * NTHREADS + tid;   // 0..639
            const int e = idx / F4T;              // 0..31
            const int c = idx % F4T;              // 0..19
            const float4 w = W4[(size_t)(et + e) * (VOCAB / 4) + vt4 + c];
            const int v = 4 * c;
            s_ts[swz(v + 0, e)] = w.x;
            s_ts[swz(v + 1, e)] = w.y;
            s_ts[swz(v + 2, e)] = w.z;
            s_ts[swz(v + 3, e)] = w.w;
        }
        __syncthreads();

        uint2* WT_u2 = (uint2*)g_WT;
        #pragma unroll
        for (int i = 0; i < 5; i++) {
            const int idx = i * NTHREADS + tid;   // 0..639
            const int v  = idx >> 3;              // 0..79
            const int e4 = idx & 7;               // 0..7
            const int e  = 4 * e4;
            __half2 h0 = __floats2half2_rn(s_ts[swz(v, e + 0)], s_ts[swz(v, e + 1)]);
            __half2 h1 = __floats2half2_rn(s_ts[swz(v, e + 2)], s_ts[swz(v, e + 3)]);
            uint2 o;
            o.x = *reinterpret_cast<unsigned int*>(&h0);
            o.y = *reinterpret_cast<unsigned int*>(&h1);
            if (vt + v == 0) { o.x = 0u; o.y = 0u; }   // mask column 0
            WT_u2[(size_t)(vt + v) * (EMBED / 4) + chunk * 8 + e4] = o;
        }
        __syncthreads();
        if (tid == 0) {
            __threadfence();
            atomicAdd(&g_ready[chunk], 1);        // release this tile
        }
    } else {
        // ---- Gather: 4 rows x 32 dims (chunk) ----
        const int row0 = tile * G_RPB;

        #pragma unroll
        for (int i = tid; i < G_RPB * K_PAD; i += NTHREADS) {
            const int r = i / K_PAD, c = i % K_PAD;
            s_ids[r * K_PAD + c] = (c < K_ITEMS)
                ? __ldg(&ids[(size_t)(row0 + r) * K_ITEMS + c]) : 0;
        }
        if (tid == 0) {
            while (ld_acquire(&g_ready[chunk]) < T_PER_CHUNK) __nanosleep(64);
        }
        __syncthreads();   // ids staged + chunk visible (acquire + barrier)

        const int lane = tid & 31;
        const int warp = tid >> 5;           // 0..3 -> row
        const int sub  = lane & 3;           // 4 lanes x 16B = 64B chunk row
        const int grp  = lane >> 2;          // 8 ids in flight per iteration
        const int row  = row0 + warp;
        const int* rids = s_ids + warp * K_PAD;

        const __half* wbase = g_WT + (size_t)chunk * ET + sub * 8;
        const __half2 z = __float2half2_rn(0.f);
        __half2 h0 = z, h1 = z, h2 = z, h3 = z;

        #pragma unroll
        for (int it = 0; it < K_PAD / 8; it++) {   // 7 iterations
            const int v = rids[it * 8 + grp];
            const int4 r = __ldg((const int4*)(wbase + (size_t)v * EMBED));
            h0 = __hadd2(h0, *reinterpret_cast<const __half2*>(&r.x));
            h1 = __hadd2(h1, *reinterpret_cast<const __half2*>(&r.y));
            h2 = __hadd2(h2, *reinterpret_cast<const __half2*>(&r.z));
            h3 = __hadd2(h3, *reinterpret_cast<const __half2*>(&r.w));
        }

        float f[8];
        { const float2 t = __half22float2(h0); f[0] = t.x; f[1] = t.y; }
        { const float2 t = __half22float2(h1); f[2] = t.x; f[3] = t.y; }
        { const float2 t = __half22float2(h2); f[4] = t.x; f[5] = t.y; }
        { const float2 t = __half22float2(h3); f[6] = t.x; f[7] = t.y; }

        #pragma unroll
        for (int m = 4; m <= 16; m <<= 1)
            #pragma unroll
            for (int i = 0; i < 8; i++)
                f[i] += __shfl_xor_sync(0xffffffffu, f[i], m);

        if (grp == 0) {
            const int b4 = chunk * 8 + sub * 2;
            const float4 b0 = __ldg((const float4*)bias + b4);
            const float4 b1 = __ldg((const float4*)bias + b4 + 1);
            float4* op = (float4*)(out + (size_t)row * EMBED) + b4;
            __stcs(op,     make_float4(f[0] + b0.x, f[1] + b0.y, f[2] + b0.z, f[3] + b0.w));
            __stcs(op + 1, make_float4(f[4] + b1.x, f[5] + b1.y, f[6] + b1.z, f[7] + b1.w));
        }
    }

    // Self-reset by the last block to finish (replay-deterministic state).
    if (tid == 0) {
        __threadfence();
        if (atomicAdd(&g_done, 1) == NBLOCKS - 1) {
            g_ready[0] = 0; g_ready[1] = 0; g_ready[2] = 0; g_ready[3] = 0;
            __threadfence();
            g_done = 0;
        }
    }
}

// ---------------------------------------------------------------------------
// Entry point. Inputs (metadata order): content_input int32, W f32, b f32.
// ---------------------------------------------------------------------------
extern "C" void kernel_launch(void* const* d_in, const int* in_sizes, int n_in,
                              void* d_out, int out_size) {
    const int*   ids = (const int*)d_in[0];
    const float* W   = (const float*)d_in[1];
    const float* b   = (const float*)d_in[2];
    float*       out = (float*)d_out;

    fused<<<NBLOCKS, NTHREADS>>>((const float4*)W, ids, b, out);
}

// round 13
// speedup vs baseline: 1.5614x; 1.5614x over previous
#include <cuda_runtime.h>
#include <cuda_fp16.h>
#include <cstdint>

#define VOCAB 100000
#define EMBED 128
#define ROWS  12800   // 64*200
#define K_ITEMS 50
#define K_PAD 52      // pad to 52 (13 iters of 4); pad ids -> 0 -> zero WT row

// 25.6 MB scratch: transposed weights WT[V][E] fp16, row 0 zeroed.
__device__ __align__(256) __half g_WT[(size_t)VOCAB * EMBED];

// ---------------------------------------------------------------------------
// Streams/events for fork-join overlap. Created once at static init (no
// device-memory allocation); same captured topology every call.
// ---------------------------------------------------------------------------
static cudaStream_t g_s2;
static cudaEvent_t  g_evT0, g_evT1, g_evG;
static struct StreamInit {
    StreamInit() {
        cudaStreamCreateWithFlags(&g_s2, cudaStreamNonBlocking);
        cudaEventCreateWithFlags(&g_evT0, cudaEventDisableTiming);
        cudaEventCreateWithFlags(&g_evT1, cudaEventDisableTiming);
        cudaEventCreateWithFlags(&g_evG,  cudaEventDisableTiming);
    }
} g_si;

// ---------------------------------------------------------------------------
// Kernel A: transpose a 64-dim E-half of W [128, 100000] fp32 -> WT fp16.
// Exact R6 tile (measured best): 32 E x 160 V, float4 loads, scalar smem
// stores with bank map v*32 + ((e + v + (v>>2)) & 31) (conflict-free both
// phases). Row v==0 of WT is zeroed (multi-hot column 0 masked).
// ---------------------------------------------------------------------------
#define VT 160
#define F4T 40
#define ET 32

__device__ __forceinline__ int swz(int v, int e) {
    return v * 32 + ((e + v + (v >> 2)) & 31);
}

__global__ __launch_bounds__(256) void transpose_W(const float4* __restrict__ W4,
                                                   int eoff) {
    __shared__ float s[VT * 32];   // 20 KB

    const int tid = threadIdx.x;
    const int vt4 = blockIdx.x * F4T;
    const int vt  = blockIdx.x * VT;
    const int et  = eoff + blockIdx.y * ET;

    #pragma unroll
    for (int i = 0; i < 5; i++) {
        const int idx = i * 256 + tid;
        const int e = idx / F4T;          // 0..31
        const int c = idx % F4T;          // 0..39
        const float4 w = W4[(size_t)(et + e) * (VOCAB / 4) + vt4 + c];
        const int v = 4 * c;
        s[swz(v + 0, e)] = w.x;
        s[swz(v + 1, e)] = w.y;
        s[swz(v + 2, e)] = w.z;
        s[swz(v + 3, e)] = w.w;
    }
    __syncthreads();

    uint2* WT_u2 = (uint2*)g_WT;          // 8 B = 4 halves
    #pragma unroll
    for (int i = 0; i < 5; i++) {
        const int idx = i * 256 + tid;
        const int v  = idx >> 3;          // 0..159
        const int e4 = idx & 7;           // 0..7
        const int e  = 4 * e4;
        __half2 h0 = __floats2half2_rn(s[swz(v, e + 0)], s[swz(v, e + 1)]);
        __half2 h1 = __floats2half2_rn(s[swz(v, e + 2)], s[swz(v, e + 3)]);
        uint2 o;
        o.x = *reinterpret_cast<unsigned int*>(&h0);
        o.y = *reinterpret_cast<unsigned int*>(&h1);
        if (vt + v == 0) { o.x = 0u; o.y = 0u; }
        WT_u2[(size_t)(vt + v) * (EMBED / 4) + (et >> 2) + e4] = o;
    }
}

// ---------------------------------------------------------------------------
// Kernel B: gather one 64-dim E-half. 1600 blocks x 256 thr, warp per row
// (8 rows/block). Lane = grp*8+sub: 8 lanes x 16B cover the 128 B row-half;
// 4 ids (grp) in flight per iteration, 13 iterations (ids padded to 52).
// fp16 HADD2 chains with one mid fp32 flush (error ~4e-4). shfl_xor(8,16)
// reduces across the 4 id-groups. Branch-free; out stored with .cs.
// ---------------------------------------------------------------------------
#define G_RPB 8
#define THREADS_B 256

__global__ __launch_bounds__(THREADS_B) void gather_chunk(
    const int* __restrict__ ids,         // [ROWS, 50] int32
    const float* __restrict__ bias,      // [128] fp32
    float* __restrict__ out,             // [ROWS, 128] fp32
    int eoff)
{
    __shared__ int s_ids[G_RPB][K_PAD];

    const int tid  = threadIdx.x;
    const int lane = tid & 31;
    const int warp = tid >> 5;           // row within block
    const int row0 = blockIdx.x * G_RPB;
    const int sub  = lane & 7;           // 16B slot within the 128B half-row
    const int grp  = lane >> 3;          // which of 4 in-flight ids

    #pragma unroll
    for (int i = tid; i < G_RPB * K_PAD; i += THREADS_B) {
        const int r = i / K_PAD, c = i % K_PAD;
        s_ids[r][c] = (c < K_ITEMS)
            ? __ldg(&ids[(size_t)(row0 + r) * K_ITEMS + c]) : 0;
    }
    __syncthreads();

    const __half* wbase = g_WT + eoff + sub * 8;
    const __half2 z = __float2half2_rn(0.f);
    __half2 h0 = z, h1 = z, h2 = z, h3 = z;
    float f[8] = {0.f, 0.f, 0.f, 0.f, 0.f, 0.f, 0.f, 0.f};

    #pragma unroll
    for (int it = 0; it < K_PAD / 4; it++) {   // 13 iterations
        const int v = s_ids[warp][it * 4 + grp];
        const int4 r = __ldg((const int4*)(wbase + (size_t)v * EMBED));
        h0 = __hadd2(h0, *reinterpret_cast<const __half2*>(&r.x));
        h1 = __hadd2(h1, *reinterpret_cast<const __half2*>(&r.y));
        h2 = __hadd2(h2, *reinterpret_cast<const __half2*>(&r.z));
        h3 = __hadd2(h3, *reinterpret_cast<const __half2*>(&r.w));
        if (it == 6) {   // mid flush keeps fp16 chains short (<=7)
            const float2 t0 = __half22float2(h0); f[0] += t0.x; f[1] += t0.y;
            const float2 t1 = __half22float2(h1); f[2] += t1.x; f[3] += t1.y;
            const float2 t2 = __half22float2(h2); f[4] += t2.x; f[5] += t2.y;
            const float2 t3 = __half22float2(h3); f[6] += t3.x; f[7] += t3.y;
            h0 = z; h1 = z; h2 = z; h3 = z;
        }
    }
    { const float2 t = __half22float2(h0); f[0] += t.x; f[1] += t.y; }
    { const float2 t = __half22float2(h1); f[2] += t.x; f[3] += t.y; }
    { const float2 t = __half22float2(h2); f[4] += t.x; f[5] += t.y; }
    { const float2 t = __half22float2(h3); f[6] += t.x; f[7] += t.y; }

    // Reduce across the 4 id-groups.
    #pragma unroll
    for (int i = 0; i < 8; i++) {
        f[i] += __shfl_xor_sync(0xffffffffu, f[i], 8);
        f[i] += __shfl_xor_sync(0xffffffffu, f[i], 16);
    }

    if (grp == 0) {
        const int b4 = (eoff >> 2) + sub * 2;      // float4 index into bias/out
        const float4 b0 = __ldg((const float4*)bias + b4);
        const float4 b1 = __ldg((const float4*)bias + b4 + 1);
        float4* op = (float4*)(out + (size_t)(row0 + warp) * EMBED) + b4;
        __stcs(op,     make_float4(f[0] + b0.x, f[1] + b0.y, f[2] + b0.z, f[3] + b0.w));
        __stcs(op + 1, make_float4(f[4] + b1.x, f[5] + b1.y, f[6] + b1.z, f[7] + b1.w));
    }
}

// ---------------------------------------------------------------------------
// Entry point. Inputs (metadata order): content_input int32, W f32, b f32.
// Fork-join: T0,T1 on the capture stream; G0,G1 on g_s2 gated by events;
// join back before return (valid capture topology, overlaps T1 with G0).
// ---------------------------------------------------------------------------
extern "C" void kernel_launch(void* const* d_in, const int* in_sizes, int n_in,
                              void* d_out, int out_size) {
    const int*   ids = (const int*)d_in[0];
    const float* W   = (const float*)d_in[1];
    const float* b   = (const float*)d_in[2];
    float*       out = (float*)d_out;

    dim3 tgrid(VOCAB / VT, 2);            // 625 x 2 per half

    transpose_W<<<tgrid, 256>>>((const float4*)W, 0);
    cudaEventRecord(g_evT0, 0);
    transpose_W<<<tgrid, 256>>>((const float4*)W, 64);
    cudaEventRecord(g_evT1, 0);

    cudaStreamWaitEvent(g_s2, g_evT0, 0);
    gather_chunk<<<ROWS / G_RPB, THREADS_B, 0, g_s2>>>(ids, b, out, 0);
    cudaStreamWaitEvent(g_s2, g_evT1, 0);
    gather_chunk<<<ROWS / G_RPB, THREADS_B, 0, g_s2>>>(ids, b, out, 64);
    cudaEventRecord(g_evG, g_s2);

    cudaStreamWaitEvent(0, g_evG, 0);     // join fork before return
}

// round 14
// speedup vs baseline: 1.8186x; 1.1648x over previous
#include <cuda_runtime.h>
#include <cuda_fp16.h>
#include <cstdint>

#define VOCAB 100000
#define EMBED 128
#define ROWS  12800   // 64*200
#define K_ITEMS 50

// 25.6 MB scratch: transposed weights WT[V][E] in fp16. Row 0 is zeroed by
// the transpose so the gather needs no id!=0 mask.
__device__ __align__(256) __half g_WT[(size_t)VOCAB * EMBED];

// ---------------------------------------------------------------------------
// Kernel A: transpose W [E=128, V=100000] (fp32) -> WT [V, E] (fp16).
// EXACT R6 tile (measured best, 10.6us): 32 E x 160 V, float4 global loads,
// scalar smem stores with bank map v*32 + ((e + v + (v>>2)) & 31)
// (conflict-free both phases). Row v==0 of WT zeroed (column 0 masked).
// WT stores use __stwt (write-through): the 25.6 MB DRAM write happens HERE,
// in the DRAM-read-bound transpose window, instead of as lazy dirty-line
// writebacks during the LTS-bound gather window.
// ---------------------------------------------------------------------------
#define VT 160        // v per tile
#define F4T 40        // float4 per e-row per tile
#define ET 32         // e per tile

__device__ __forceinline__ int swz(int v, int e) {
    return v * 32 + ((e + v + (v >> 2)) & 31);
}

__global__ __launch_bounds__(256) void transpose_W(const float4* __restrict__ W4) {
    __shared__ float s[VT * 32];   // 20 KB

    const int tid = threadIdx.x;
    const int vt4 = blockIdx.x * F4T;    // float4 offset along V
    const int vt  = blockIdx.x * VT;     // float offset along V
    const int et  = blockIdx.y * ET;     // float offset along E

    #pragma unroll
    for (int i = 0; i < 5; i++) {
        const int idx = i * 256 + tid;
        const int e = idx / F4T;          // 0..31
        const int c = idx % F4T;          // 0..39
        const float4 w = W4[(size_t)(et + e) * (VOCAB / 4) + vt4 + c];
        const int v = 4 * c;
        s[swz(v + 0, e)] = w.x;
        s[swz(v + 1, e)] = w.y;
        s[swz(v + 2, e)] = w.z;
        s[swz(v + 3, e)] = w.w;
    }
    __syncthreads();

    uint2* WT_u2 = (uint2*)g_WT;          // 8 B = 4 halves per element
    #pragma unroll
    for (int i = 0; i < 5; i++) {
        const int idx = i * 256 + tid;
        const int v  = idx >> 3;          // 0..159
        const int e4 = idx & 7;           // 0..7
        const int e  = 4 * e4;
        __half2 h0 = __floats2half2_rn(s[swz(v, e + 0)], s[swz(v, e + 1)]);
        __half2 h1 = __floats2half2_rn(s[swz(v, e + 2)], s[swz(v, e + 3)]);
        uint2 o;
        o.x = *reinterpret_cast<unsigned int*>(&h0);
        o.y = *reinterpret_cast<unsigned int*>(&h1);
        if (vt + v == 0) { o.x = 0u; o.y = 0u; }   // mask column 0
        __stwt(&WT_u2[(size_t)(vt + v) * (EMBED / 4) + (et >> 2) + e4], o);
    }
}

// ---------------------------------------------------------------------------
// Kernel B: embedding-bag gather from fp16 WT (EXACT R10 config: measured
// best at 15.52us). 3200 blocks x 128 thr (4 rows/block, warp per row).
// Half-warp fetches one full 256 B WT row via LDG.128 (2 ids/iteration,
// 25 iterations in 5 groups of 5). fp16 HADD2 within a group, fp32 across
// groups. Branch-free (WT row 0 zero). shfl_xor(16) merges half-warp
// partials. Out stored with .cs (single-use).
// ---------------------------------------------------------------------------
#define ROWS_PER_BLOCK 4
#define THREADS_B (ROWS_PER_BLOCK * 32)

__global__ __launch_bounds__(THREADS_B) void gather_rows(
    const int* __restrict__ ids,         // [ROWS, 50] int32
    const float* __restrict__ bias,      // [128] fp32
    float* __restrict__ out)             // [ROWS, 128] fp32
{
    __shared__ int s_ids[ROWS_PER_BLOCK][K_ITEMS];

    const int tid  = threadIdx.x;
    const int lane = tid & 31;
    const int wrow = tid >> 5;
    const int row0 = blockIdx.x * ROWS_PER_BLOCK;
    const int sub  = lane & 15;          // lane within half-warp
    const int half = lane >> 4;          // which id of the pair

    const int* gids = ids + (size_t)row0 * K_ITEMS;
    #pragma unroll
    for (int i = tid; i < ROWS_PER_BLOCK * K_ITEMS; i += THREADS_B) {
        s_ids[i / K_ITEMS][i % K_ITEMS] = gids[i];
    }
    __syncthreads();

    float a0 = 0.f, a1 = 0.f, a2 = 0.f, a3 = 0.f;
    float a4 = 0.f, a5 = 0.f, a6 = 0.f, a7 = 0.f;

    #pragma unroll
    for (int g = 0; g < 5; g++) {
        const __half2 z = __float2half2_rn(0.f);
        __half2 h0 = z, h1 = z, h2 = z, h3 = z;

        #pragma unroll
        for (int j = 0; j < 5; j++) {
            const int v = s_ids[wrow][10 * g + 2 * j + half];
            const int4 r = __ldg((const int4*)(g_WT + (size_t)v * EMBED) + sub);
            h0 = __hadd2(h0, *reinterpret_cast<const __half2*>(&r.x));
            h1 = __hadd2(h1, *reinterpret_cast<const __half2*>(&r.y));
            h2 = __hadd2(h2, *reinterpret_cast<const __half2*>(&r.z));
            h3 = __hadd2(h3, *reinterpret_cast<const __half2*>(&r.w));
        }

        const float2 f0 = __half22float2(h0);
        const float2 f1 = __half22float2(h1);
        const float2 f2 = __half22float2(h2);
        const float2 f3 = __half22float2(h3);
        a0 += f0.x; a1 += f0.y; a2 += f1.x; a3 += f1.y;
        a4 += f2.x; a5 += f2.y; a6 += f3.x; a7 += f3.y;
    }

    // Merge the two half-warp partial sums (each covered different ids).
    a0 += __shfl_xor_sync(0xffffffffu, a0, 16);
    a1 += __shfl_xor_sync(0xffffffffu, a1, 16);
    a2 += __shfl_xor_sync(0xffffffffu, a2, 16);
    a3 += __shfl_xor_sync(0xffffffffu, a3, 16);
    a4 += __shfl_xor_sync(0xffffffffu, a4, 16);
    a5 += __shfl_xor_sync(0xffffffffu, a5, 16);
    a6 += __shfl_xor_sync(0xffffffffu, a6, 16);
    a7 += __shfl_xor_sync(0xffffffffu, a7, 16);

    // Lane writes float4 slot j = 2*sub + half (dims 8*sub + 4*half ..+3).
    const int j = 2 * sub + half;
    float4 o = (half == 0) ? make_float4(a0, a1, a2, a3)
                           : make_float4(a4, a5, a6, a7);
    const float4 bv = __ldg((const float4*)bias + j);
    o.x += bv.x; o.y += bv.y; o.z += bv.z; o.w += bv.w;
    __stcs((float4*)(out + (size_t)(row0 + wrow) * EMBED) + j, o);
}

// ---------------------------------------------------------------------------
// Entry point. Inputs (metadata order): content_input int32, W f32, b f32.
// ---------------------------------------------------------------------------
extern "C" void kernel_launch(void* const* d_in, const int* in_sizes, int n_in,
                              void* d_out, int out_size) {
    const int*   ids = (const int*)d_in[0];
    const float* W   = (const float*)d_in[1];
    const float* b   = (const float*)d_in[2];
    float*       out = (float*)d_out;

    dim3 tgrid(VOCAB / VT, EMBED / ET);   // 625 x 4
    transpose_W<<<tgrid, 256>>>((const float4*)W);

    gather_rows<<<ROWS / ROWS_PER_BLOCK, THREADS_B>>>(ids, b, out);
}